// round 12
// baseline (speedup 1.0000x reference)
#include <cuda_runtime.h>
#include <math.h>
#include <stdint.h>

// ---------------- problem constants ----------------
#define NTOK  50176        // B*T
#define TSEQ  3136
#define BATCH 16
#define LN_EPS 1e-5f
#define EPS    1e-8f

// ---------------- device scratch (no mallocs allowed) ----------------
__device__ float g_h   [(size_t)NTOK * 512];
__device__ float g_kqv [(size_t)NTOK * 1536];
__device__ float g_kp  [(size_t)NTOK * 256];
__device__ float g_qp  [(size_t)NTOK * 256];
__device__ float g_xdk [NTOK];
__device__ float g_xdq [NTOK];
__device__ float g_part[BATCH * 28 * 256];
__device__ float g_kpsum[BATCH * 256];
__device__ float g_kptv[(size_t)BATCH * 512 * 256];
__device__ float g_D   [NTOK];
__device__ float g_y   [(size_t)NTOK * 512];
__device__ float g_x2  [(size_t)NTOK * 512];
__device__ float g_h2  [(size_t)NTOK * 512];
__device__ float g_u   [(size_t)NTOK * 512];

// =====================================================================
// tf32x3 tensor-core GEMM (fp32-accurate via hi/lo split, 3 MMAs)
// C[M,N] = epi(A @ B); A[M,K] row-major, B[K,N] row-major, fp32 in/out.
// Requires M%128==0, N%128==0, K%8==0 (true for all 4 call sites).
// EPI 0: +bias   EPI 3: +bias+res   EPI 4: gelu_exact(+bias)
// =====================================================================
__device__ __forceinline__ void tf32_split(float x, float& hi, float& lo)
{
    uint32_t u;
    asm("cvt.rna.tf32.f32 %0, %1;" : "=r"(u) : "f"(x));
    hi = __uint_as_float(u);
    float r = x - hi;
    asm("cvt.rna.tf32.f32 %0, %1;" : "=r"(u) : "f"(r));
    lo = __uint_as_float(u);
}

__device__ __forceinline__ void mma_tf32(float* c, const float* a, const float* b)
{
    asm volatile(
        "mma.sync.aligned.m16n8k8.row.col.f32.tf32.tf32.f32 "
        "{%0,%1,%2,%3}, {%4,%5,%6,%7}, {%8,%9}, {%0,%1,%2,%3};"
        : "+f"(c[0]), "+f"(c[1]), "+f"(c[2]), "+f"(c[3])
        : "r"(__float_as_uint(a[0])), "r"(__float_as_uint(a[1])),
          "r"(__float_as_uint(a[2])), "r"(__float_as_uint(a[3])),
          "r"(__float_as_uint(b[0])), "r"(__float_as_uint(b[1])));
}

template<int EPI>
__global__ void __launch_bounds__(256)
gemm_tf32_kernel(const float* __restrict__ A, const float* __restrict__ B,
                 float* __restrict__ C, int Mrows, int Ncols, int K,
                 const float* __restrict__ bias, const float* __restrict__ res)
{
    constexpr int BM = 128, BN = 128, BK = 8;
    // [buf][k][m/n] with +4 pad to spread banks
    __shared__ float Ah[2][BK][BM + 4], Al[2][BK][BM + 4];
    __shared__ float Bh[2][BK][BN + 4], Bl[2][BK][BN + 4];

    const int tid  = threadIdx.x;
    const int row0 = blockIdx.y * BM, col0 = blockIdx.x * BN;
    const int lda = K, ldb = Ncols, ldc = Ncols;

    // gmem load mapping (float4 each for A and B per thread)
    const int arow  = tid >> 1;            // 0..127
    const int acol4 = (tid & 1) * 4;       // 0 or 4 within BK=8
    const int brow  = tid >> 5;            // 0..7
    const int bcol4 = (tid & 31) * 4;      // 0..124

    // warp/fragment mapping
    const int warp = tid >> 5, lane = tid & 31;
    const int wm = warp & 1, wn = warp >> 1;       // 2 x 4 warp grid
    const int g = lane >> 2, tg = lane & 3;
    const int m_base = wm * 64, n_base = wn * 32;

    float c[4][4][4];
#pragma unroll
    for (int mt = 0; mt < 4; mt++)
#pragma unroll
        for (int nt = 0; nt < 4; nt++)
#pragma unroll
            for (int e = 0; e < 4; e++) c[mt][nt][e] = 0.f;

    auto stage = [&](int buf, float4 av, float4 bv) {
        float hi, lo;
        float a[4] = {av.x, av.y, av.z, av.w};
        float b[4] = {bv.x, bv.y, bv.z, bv.w};
#pragma unroll
        for (int j = 0; j < 4; j++) {
            tf32_split(a[j], hi, lo);
            Ah[buf][acol4 + j][arow] = hi;
            Al[buf][acol4 + j][arow] = lo;
        }
#pragma unroll
        for (int j = 0; j < 4; j++) {
            tf32_split(b[j], hi, lo);
            Bh[buf][brow][bcol4 + j] = hi;
            Bl[buf][brow][bcol4 + j] = lo;
        }
    };

    // ---- preload k0 = 0 ----
    {
        float4 av = *(const float4*)&A[(size_t)(row0 + arow) * lda + acol4];
        float4 bv = *(const float4*)&B[(size_t)brow * ldb + col0 + bcol4];
        stage(0, av, bv);
    }
    __syncthreads();

    int cur = 0;
    for (int k0 = 0; k0 < K; k0 += BK) {
        const bool more = (k0 + BK) < K;
        float4 av, bv;
        if (more) {
            av = *(const float4*)&A[(size_t)(row0 + arow) * lda + k0 + BK + acol4];
            bv = *(const float4*)&B[(size_t)(k0 + BK + brow) * ldb + col0 + bcol4];
        }

        // ---- load fragments from smem ----
        float ah[4][4], al[4][4], bh[4][2], bl[4][2];
#pragma unroll
        for (int mt = 0; mt < 4; mt++) {
            int m0 = m_base + mt * 16 + g;
            ah[mt][0] = Ah[cur][tg    ][m0];
            ah[mt][1] = Ah[cur][tg    ][m0 + 8];
            ah[mt][2] = Ah[cur][tg + 4][m0];
            ah[mt][3] = Ah[cur][tg + 4][m0 + 8];
            al[mt][0] = Al[cur][tg    ][m0];
            al[mt][1] = Al[cur][tg    ][m0 + 8];
            al[mt][2] = Al[cur][tg + 4][m0];
            al[mt][3] = Al[cur][tg + 4][m0 + 8];
        }
#pragma unroll
        for (int nt = 0; nt < 4; nt++) {
            int n0 = n_base + nt * 8 + g;
            bh[nt][0] = Bh[cur][tg    ][n0];
            bh[nt][1] = Bh[cur][tg + 4][n0];
            bl[nt][0] = Bl[cur][tg    ][n0];
            bl[nt][1] = Bl[cur][tg + 4][n0];
        }

        // ---- 3-pass tf32 MMA: hi*hi + hi*lo + lo*hi ----
#pragma unroll
        for (int mt = 0; mt < 4; mt++)
#pragma unroll
            for (int nt = 0; nt < 4; nt++) {
                mma_tf32(c[mt][nt], ah[mt], bh[nt]);
                mma_tf32(c[mt][nt], ah[mt], bl[nt]);
                mma_tf32(c[mt][nt], al[mt], bh[nt]);
            }

        if (more) stage(cur ^ 1, av, bv);
        __syncthreads();
        cur ^= 1;
    }

    // ---- epilogue ----
#pragma unroll
    for (int mt = 0; mt < 4; mt++) {
#pragma unroll
        for (int nt = 0; nt < 4; nt++) {
            int r0 = row0 + m_base + mt * 16 + g;
            int cc = col0 + n_base + nt * 8 + tg * 2;
#pragma unroll
            for (int half = 0; half < 2; half++) {
                int r = r0 + half * 8;
                float v0 = c[mt][nt][half * 2 + 0];
                float v1 = c[mt][nt][half * 2 + 1];
                if (EPI == 0) { v0 += bias[cc]; v1 += bias[cc + 1]; }
                else if (EPI == 3) {
                    v0 += bias[cc]     + res[(size_t)r * ldc + cc];
                    v1 += bias[cc + 1] + res[(size_t)r * ldc + cc + 1];
                }
                else if (EPI == 4) {
                    float t0 = v0 + bias[cc];
                    float t1 = v1 + bias[cc + 1];
                    v0 = 0.5f * t0 * (1.f + erff(t0 * 0.70710678118654752f));
                    v1 = 0.5f * t1 * (1.f + erff(t1 * 0.70710678118654752f));
                }
                *(float2*)&C[(size_t)r * ldc + cc] = make_float2(v0, v1);
            }
        }
    }
    (void)Mrows;
}

// =====================================================================
// generic tiled fp32 GEMM (double-buffered smem) — used for kp/qp/kptv/y
// =====================================================================
template<int AMODE, int BMODE, int EPI>
__global__ void __launch_bounds__(256)
gemm_kernel(const float* __restrict__ A, const float* __restrict__ B,
            float* __restrict__ C,
            int Mrows, int Ncols, int K,
            int lda, int ldb, int ldc,
            const float* __restrict__ bias,
            const float* __restrict__ rowv,
            const float* __restrict__ res,
            long long sA, long long sB, long long sC, long long sRow)
{
    constexpr int BM = 128, BN = 128, BK = 16, TM = 8, TN = 8;
    __shared__ float As[2][BM][BK + 1];
    __shared__ __align__(16) float Bs[2][BK][BN + 4];

    const int z = blockIdx.z;
    A += (long long)z * sA;
    B += (long long)z * sB;
    C += (long long)z * sC;
    const float* rv = rowv ? rowv + (long long)z * sRow : nullptr;

    const int bx = blockIdx.x, by = blockIdx.y;
    const int tid = threadIdx.x;
    const int tx = tid & 15, ty = tid >> 4;
    const int row0 = by * BM, col0 = bx * BN;

    int am[8], ak[8], bn[8], bk[8];
#pragma unroll
    for (int l = 0; l < 8; l++) {
        int linear = tid + l * 256;
        if (AMODE == 0) { am[l] = linear >> 4;  ak[l] = linear & 15;  }
        else            { ak[l] = linear >> 7;  am[l] = linear & 127; }
        if (BMODE == 0) { bk[l] = linear >> 7;  bn[l] = linear & 127; }
        else            { bn[l] = linear >> 4;  bk[l] = linear & 15;  }
    }

    auto fetchA = [&](int l, int k0) -> float {
        int gm = row0 + am[l], gk = k0 + ak[l];
        if (gm >= Mrows || gk >= K) return 0.f;
        return (AMODE == 0) ? A[(size_t)gm * lda + gk] : A[(size_t)gk * lda + gm];
    };
    auto fetchB = [&](int l, int k0) -> float {
        int gk = k0 + bk[l], gn = col0 + bn[l];
        if (gk >= K || gn >= Ncols) return 0.f;
        return (BMODE == 0) ? B[(size_t)gk * ldb + gn] : B[(size_t)gn * ldb + gk];
    };

    float acc[TM][TN];
#pragma unroll
    for (int i = 0; i < TM; i++)
#pragma unroll
        for (int j = 0; j < TN; j++) acc[i][j] = 0.f;

#pragma unroll
    for (int l = 0; l < 8; l++) {
        As[0][am[l]][ak[l]] = fetchA(l, 0);
        Bs[0][bk[l]][bn[l]] = fetchB(l, 0);
    }
    __syncthreads();

    int cur = 0;
    for (int k0 = 0; k0 < K; k0 += BK) {
        float pa[8], pb[8];
        const bool more = (k0 + BK) < K;
        if (more) {
#pragma unroll
            for (int l = 0; l < 8; l++) {
                pa[l] = fetchA(l, k0 + BK);
                pb[l] = fetchB(l, k0 + BK);
            }
        }

#pragma unroll
        for (int kk = 0; kk < BK; ++kk) {
            float a[TM];
#pragma unroll
            for (int i = 0; i < TM; i++) a[i] = As[cur][ty * TM + i][kk];
            float4 b0 = *(const float4*)&Bs[cur][kk][tx * TN];
            float4 b1 = *(const float4*)&Bs[cur][kk][tx * TN + 4];
            float b[TN] = {b0.x, b0.y, b0.z, b0.w, b1.x, b1.y, b1.z, b1.w};
#pragma unroll
            for (int i = 0; i < TM; i++)
#pragma unroll
                for (int j = 0; j < TN; j++) acc[i][j] += a[i] * b[j];
        }

        if (more) {
            int nxt = cur ^ 1;
#pragma unroll
            for (int l = 0; l < 8; l++) {
                As[nxt][am[l]][ak[l]] = pa[l];
                Bs[nxt][bk[l]][bn[l]] = pb[l];
            }
        }
        __syncthreads();
        cur ^= 1;
    }

#pragma unroll
    for (int i = 0; i < TM; i++) {
        int r = row0 + ty * TM + i;
        if (r >= Mrows) continue;
        float rvv = 0.f;
        if (EPI == 1 || EPI == 2) rvv = rv[r];
#pragma unroll
        for (int j = 0; j < TN; j++) {
            int c = col0 + tx * TN + j;
            if (c >= Ncols) continue;
            float v = acc[i][j];
            if (EPI == 0)      { if (bias) v += bias[c]; }
            else if (EPI == 1) { v = expf(v - rvv) * 0.0625f; }
            else if (EPI == 2) { v = v / (rvv + EPS); }
            else if (EPI == 3) { v = v + bias[c] + res[(size_t)r * ldc + c]; }
            else if (EPI == 4) { float t = v + bias[c];
                                 v = 0.5f * t * (1.f + erff(t * 0.70710678118654752f)); }
            C[(size_t)r * ldc + c] = v;
        }
    }
}

// ---------------- LayerNorm: one warp per token, dim 512 ----------------
__global__ void ln_kernel(const float* __restrict__ x, const float* __restrict__ g,
                          const float* __restrict__ b, float* __restrict__ out)
{
    int warp = blockIdx.x * 8 + (threadIdx.x >> 5);
    int lane = threadIdx.x & 31;
    if (warp >= NTOK) return;
    const float* row = x + (size_t)warp * 512;
    float v[16], s = 0.f, s2 = 0.f;
#pragma unroll
    for (int i = 0; i < 16; i++) {
        v[i] = row[lane + i * 32];
        s += v[i]; s2 += v[i] * v[i];
    }
#pragma unroll
    for (int o = 16; o; o >>= 1) {
        s  += __shfl_xor_sync(0xffffffffu, s,  o);
        s2 += __shfl_xor_sync(0xffffffffu, s2, o);
    }
    float mu  = s * (1.f / 512.f);
    float var = s2 * (1.f / 512.f) - mu * mu;
    float inv = rsqrtf(var + LN_EPS);
    float* orow = out + (size_t)warp * 512;
#pragma unroll
    for (int i = 0; i < 16; i++) {
        int c = lane + i * 32;
        orow[c] = (v[i] - mu) * inv * g[c] + b[c];
    }
}

// ---------------- xd = 0.5*||k||^2 and 0.5*||q||^2 per token ----------------
__global__ void xd_kernel(const float* __restrict__ kqv,
                          float* __restrict__ xdk, float* __restrict__ xdq)
{
    int warp = blockIdx.x * 8 + (threadIdx.x >> 5);
    int lane = threadIdx.x & 31;
    if (warp >= NTOK) return;
    const float* r = kqv + (size_t)warp * 1536;
    float sk = 0.f, sq = 0.f;
#pragma unroll
    for (int i = 0; i < 16; i++) {
        float a = r[lane + i * 32];        sk += a * a;
        float b = r[512 + lane + i * 32];  sq += b * b;
    }
#pragma unroll
    for (int o = 16; o; o >>= 1) {
        sk += __shfl_xor_sync(0xffffffffu, sk, o);
        sq += __shfl_xor_sync(0xffffffffu, sq, o);
    }
    if (lane == 0) { xdk[warp] = 0.5f * sk; xdq[warp] = 0.5f * sq; }
}

// ---------------- kp column-sum over T (deterministic two-stage) ----------------
__global__ void kpsum_stage1(const float* __restrict__ kp, float* __restrict__ part)
{
    int b = blockIdx.x, chunk = blockIdx.y, m = threadIdx.x;   // 256 threads
    int t0 = chunk * 112;
    float s = 0.f;
    const float* base = kp + ((size_t)b * TSEQ + t0) * 256 + m;
    for (int t = 0; t < 112; ++t) s += base[(size_t)t * 256];
    part[((size_t)b * 28 + chunk) * 256 + m] = s;
}
__global__ void kpsum_stage2(const float* __restrict__ part, float* __restrict__ kpsum)
{
    int b = blockIdx.x, m = threadIdx.x;
    float s = 0.f;
#pragma unroll
    for (int c = 0; c < 28; ++c) s += part[((size_t)b * 28 + c) * 256 + m];
    kpsum[b * 256 + m] = s;
}

// ---------------- D[t] = qp[t,:] . kpsum[b,:] : one warp per token ----------------
__global__ void d_kernel(const float* __restrict__ qp, const float* __restrict__ kpsum,
                         float* __restrict__ D)
{
    int warp = blockIdx.x * 8 + (threadIdx.x >> 5);
    int lane = threadIdx.x & 31;
    if (warp >= NTOK) return;
    int b = warp / TSEQ;
    const float* q  = qp + (size_t)warp * 256;
    const float* ks = kpsum + b * 256;
    float s = 0.f;
#pragma unroll
    for (int i = 0; i < 8; i++) {
        int c = lane + i * 32;
        s += q[c] * ks[c];
    }
#pragma unroll
    for (int o = 16; o; o >>= 1) s += __shfl_xor_sync(0xffffffffu, s, o);
    if (lane == 0) D[warp] = s;
}

// ---------------- host launch ----------------
extern "C" void kernel_launch(void* const* d_in, const int* in_sizes, int n_in,
                              void* d_out, int out_size)
{
    const float* x      = (const float*)d_in[0];
    const float* w_kqv  = (const float*)d_in[1];
    const float* b_kqv  = (const float*)d_in[2];
    const float* w_proj = (const float*)d_in[3];
    const float* b_proj = (const float*)d_in[4];
    const float* g1     = (const float*)d_in[5];
    const float* be1    = (const float*)d_in[6];
    const float* g2     = (const float*)d_in[7];
    const float* be2    = (const float*)d_in[8];
    const float* w_mlp1 = (const float*)d_in[9];
    const float* b_mlp1 = (const float*)d_in[10];
    const float* w_mlp2 = (const float*)d_in[11];
    const float* b_mlp2 = (const float*)d_in[12];
    const float* w_rand = (const float*)d_in[13];
    float* out = (float*)d_out;

    float *h, *kqv, *kp, *qp, *xdk, *xdq, *part, *kpsum, *kptv, *Dv, *y, *x2, *h2, *u;
    cudaGetSymbolAddress((void**)&h,    g_h);
    cudaGetSymbolAddress((void**)&kqv,  g_kqv);
    cudaGetSymbolAddress((void**)&kp,   g_kp);
    cudaGetSymbolAddress((void**)&qp,   g_qp);
    cudaGetSymbolAddress((void**)&xdk,  g_xdk);
    cudaGetSymbolAddress((void**)&xdq,  g_xdq);
    cudaGetSymbolAddress((void**)&part, g_part);
    cudaGetSymbolAddress((void**)&kpsum,g_kpsum);
    cudaGetSymbolAddress((void**)&kptv, g_kptv);
    cudaGetSymbolAddress((void**)&Dv,   g_D);
    cudaGetSymbolAddress((void**)&y,    g_y);
    cudaGetSymbolAddress((void**)&x2,   g_x2);
    cudaGetSymbolAddress((void**)&h2,   g_h2);
    cudaGetSymbolAddress((void**)&u,    g_u);

    // 1) h = LN1(x)
    ln_kernel<<<NTOK / 8, 256>>>(x, g1, be1, h);

    // 2) kqv = h @ w_kqv + b_kqv                     [50176,1536]  (tf32x3)
    gemm_tf32_kernel<0><<<dim3(12, 392), 256>>>(
        h, w_kqv, kqv, NTOK, 1536, 512, b_kqv, nullptr);

    // 3) xd_k, xd_q
    xd_kernel<<<NTOK / 8, 256>>>(kqv, xdk, xdq);

    // 4) kp = exp(k @ w_rand^T - xd_k)/16            [50176,256]  (fp32)
    gemm_kernel<0,1,1><<<dim3(2, 392, 1), 256>>>(
        kqv, w_rand, kp, NTOK, 256, 512, 1536, 512, 256,
        nullptr, xdk, nullptr, 0, 0, 0, 0);

    // 5) qp = exp(q @ w_rand^T - xd_q)/16            (fp32)
    gemm_kernel<0,1,1><<<dim3(2, 392, 1), 256>>>(
        kqv + 512, w_rand, qp, NTOK, 256, 512, 1536, 512, 256,
        nullptr, xdq, nullptr, 0, 0, 0, 0);

    // 6) kpsum[b,m] = sum_t kp   (deterministic two-stage)
    kpsum_stage1<<<dim3(BATCH, 28, 1), 256>>>(kp, part);
    kpsum_stage2<<<BATCH, 256>>>(part, kpsum);

    // 7) kptv[b,n,m] = sum_t v[b,t,n]*kp[b,t,m]      per-batch TN GEMM (fp32)
    gemm_kernel<1,0,0><<<dim3(2, 4, BATCH), 256>>>(
        kqv + 1024, kp, kptv, 512, 256, TSEQ, 1536, 256, 256,
        nullptr, nullptr, nullptr,
        (long long)TSEQ * 1536, (long long)TSEQ * 256, (long long)512 * 256, 0);

    // 8) D[t] = qp . kpsum
    d_kernel<<<NTOK / 8, 256>>>(qp, kpsum, Dv);

    // 9) y = (qp @ kptv^T) / (D + eps)               per-batch GEMM (fp32)
    gemm_kernel<0,1,2><<<dim3(4, 25, BATCH), 256>>>(
        qp, kptv, y, TSEQ, 512, 256, 256, 256, 512,
        nullptr, Dv, nullptr,
        (long long)TSEQ * 256, (long long)512 * 256, (long long)TSEQ * 512, TSEQ);

    // 10) x2 = y @ w_proj + b_proj + x (residual)    (tf32x3)
    gemm_tf32_kernel<3><<<dim3(4, 392), 256>>>(
        y, w_proj, x2, NTOK, 512, 512, b_proj, x);

    // 11) h2 = LN2(x2)
    ln_kernel<<<NTOK / 8, 256>>>(x2, g2, be2, h2);

    // 12) u = gelu(h2 @ w_mlp1 + b_mlp1)             (tf32x3)
    gemm_tf32_kernel<4><<<dim3(4, 392), 256>>>(
        h2, w_mlp1, u, NTOK, 512, 512, b_mlp1, nullptr);

    // 13) out = u @ w_mlp2 + b_mlp2 + x2 (residual)  (tf32x3)
    gemm_tf32_kernel<3><<<dim3(4, 392), 256>>>(
        u, w_mlp2, out, NTOK, 512, 512, b_mlp2, x2);

    (void)in_sizes; (void)n_in; (void)out_size;
}

// round 15
// speedup vs baseline: 1.1503x; 1.1503x over previous
#include <cuda_runtime.h>
#include <math.h>
#include <stdint.h>

// ---------------- problem constants ----------------
#define NTOK  50176        // B*T
#define TSEQ  3136
#define BATCH 16
#define LN_EPS 1e-5f
#define EPS    1e-8f

// ---------------- device scratch (no mallocs allowed) ----------------
__device__ float g_h   [(size_t)NTOK * 512];
__device__ float g_kqv [(size_t)NTOK * 1536];
__device__ float g_kp  [(size_t)NTOK * 256];
__device__ float g_qp  [(size_t)NTOK * 256];
__device__ float g_xdk [NTOK];
__device__ float g_xdq [NTOK];
__device__ float g_part[BATCH * 28 * 256];
__device__ float g_kpsum[BATCH * 256];
__device__ float g_kptv[(size_t)BATCH * 512 * 256];
__device__ float g_D   [NTOK];
__device__ float g_y   [(size_t)NTOK * 512];
__device__ float g_x2  [(size_t)NTOK * 512];
__device__ float g_h2  [(size_t)NTOK * 512];
__device__ float g_u   [(size_t)NTOK * 512];

// =====================================================================
// tf32x3 tensor-core GEMM (fp32-accurate via hi/lo split, 3 MMAs)
// C[M,N] = epi(A @ B), fp32 in/out.
// AMODE 0: A[m*lda+k]      AMODE 1: A[k*lda+m]  (A^T given; requires M%128==0)
// BMODE 0: B[k*ldb+n]      BMODE 1: B[n*ldb+k]  (B^T given; requires N%128==0)
// Requires N%128==0, K%8==0. M guarded (any M).
// EPI 0: +bias  1: exp(acc-rowv[r])/16  2: acc/(rowv[r]+EPS)
// EPI 3: +bias+res  4: gelu_exact(+bias)  5: none
// =====================================================================
__device__ __forceinline__ void tf32_split(float x, float& hi, float& lo)
{
    uint32_t u;
    asm("cvt.rna.tf32.f32 %0, %1;" : "=r"(u) : "f"(x));
    hi = __uint_as_float(u);
    float r = x - hi;
    asm("cvt.rna.tf32.f32 %0, %1;" : "=r"(u) : "f"(r));
    lo = __uint_as_float(u);
}

__device__ __forceinline__ void mma_tf32(float* c, const float* a, const float* b)
{
    asm volatile(
        "mma.sync.aligned.m16n8k8.row.col.f32.tf32.tf32.f32 "
        "{%0,%1,%2,%3}, {%4,%5,%6,%7}, {%8,%9}, {%0,%1,%2,%3};"
        : "+f"(c[0]), "+f"(c[1]), "+f"(c[2]), "+f"(c[3])
        : "r"(__float_as_uint(a[0])), "r"(__float_as_uint(a[1])),
          "r"(__float_as_uint(a[2])), "r"(__float_as_uint(a[3])),
          "r"(__float_as_uint(b[0])), "r"(__float_as_uint(b[1])));
}

template<int AMODE, int BMODE, int EPI>
__global__ void __launch_bounds__(256)
gemm_tf32(const float* __restrict__ A, const float* __restrict__ B,
          float* __restrict__ C,
          int Mrows, int Ncols, int K, int lda, int ldb, int ldc,
          const float* __restrict__ bias,
          const float* __restrict__ rowv,
          const float* __restrict__ res,
          long long sA, long long sB, long long sC, long long sRow)
{
    constexpr int BM = 128, BN = 128, BK = 8;
    __shared__ float Ah[2][BK][BM + 4], Al[2][BK][BM + 4];
    __shared__ float Bh[2][BK][BN + 4], Bl[2][BK][BN + 4];

    const int z = blockIdx.z;
    A += (long long)z * sA;
    B += (long long)z * sB;
    C += (long long)z * sC;
    const float* rv = rowv ? rowv + (long long)z * sRow : nullptr;

    const int tid  = threadIdx.x;
    const int row0 = blockIdx.y * BM, col0 = blockIdx.x * BN;

    // ---- gmem load mapping (one float4 for A, one for B, per thread) ----
    const int arow  = (AMODE == 0) ? (tid >> 1) : 0;
    const int acol4 = (AMODE == 0) ? ((tid & 1) * 4) : 0;
    const int ak    = (AMODE == 1) ? (tid >> 5) : 0;
    const int am4   = (AMODE == 1) ? ((tid & 31) * 4) : 0;
    const int bk    = (BMODE == 0) ? (tid >> 5) : 0;
    const int bn4   = (BMODE == 0) ? ((tid & 31) * 4) : 0;
    const int bn    = (BMODE == 1) ? (tid >> 1) : 0;
    const int bk4   = (BMODE == 1) ? ((tid & 1) * 4) : 0;

    // warp/fragment mapping (verified: rel_err 8.6e-7 on round-12 pass)
    const int warp = tid >> 5, lane = tid & 31;
    const int wm = warp & 1, wn = warp >> 1;       // 2 x 4 warp grid
    const int g = lane >> 2, tg = lane & 3;
    const int m_base = wm * 64, n_base = wn * 32;

    float c[4][4][4];
#pragma unroll
    for (int mt = 0; mt < 4; mt++)
#pragma unroll
        for (int nt = 0; nt < 4; nt++)
#pragma unroll
            for (int e = 0; e < 4; e++) c[mt][nt][e] = 0.f;

    auto loadA = [&](int k0) -> float4 {
        if (AMODE == 0) {
            int gm = row0 + arow;
            if (gm < Mrows)
                return *(const float4*)&A[(size_t)gm * lda + k0 + acol4];
            return make_float4(0.f, 0.f, 0.f, 0.f);
        } else {
            // AMODE 1 requires M%128==0 (call site: kptv M=512)
            return *(const float4*)&A[(size_t)(k0 + ak) * lda + row0 + am4];
        }
    };
    auto loadB = [&](int k0) -> float4 {
        if (BMODE == 0)
            return *(const float4*)&B[(size_t)(k0 + bk) * ldb + col0 + bn4];
        else
            return *(const float4*)&B[(size_t)(col0 + bn) * ldb + k0 + bk4];
    };
    auto stage = [&](int buf, float4 av, float4 bv) {
        float hi, lo;
        float a[4] = {av.x, av.y, av.z, av.w};
        float b[4] = {bv.x, bv.y, bv.z, bv.w};
#pragma unroll
        for (int j = 0; j < 4; j++) {
            tf32_split(a[j], hi, lo);
            if (AMODE == 0) { Ah[buf][acol4 + j][arow] = hi; Al[buf][acol4 + j][arow] = lo; }
            else            { Ah[buf][ak][am4 + j]     = hi; Al[buf][ak][am4 + j]     = lo; }
        }
#pragma unroll
        for (int j = 0; j < 4; j++) {
            tf32_split(b[j], hi, lo);
            if (BMODE == 0) { Bh[buf][bk][bn4 + j] = hi; Bl[buf][bk][bn4 + j] = lo; }
            else            { Bh[buf][bk4 + j][bn] = hi; Bl[buf][bk4 + j][bn] = lo; }
        }
    };

    // ---- preload k0 = 0 ----
    stage(0, loadA(0), loadB(0));
    __syncthreads();

    int cur = 0;
    for (int k0 = 0; k0 < K; k0 += BK) {
        const bool more = (k0 + BK) < K;
        float4 av, bv;
        if (more) { av = loadA(k0 + BK); bv = loadB(k0 + BK); }

        // ---- load fragments from smem ----
        float ah[4][4], al[4][4], bh[4][2], bl[4][2];
#pragma unroll
        for (int mt = 0; mt < 4; mt++) {
            int m0 = m_base + mt * 16 + g;
            ah[mt][0] = Ah[cur][tg    ][m0];
            ah[mt][1] = Ah[cur][tg    ][m0 + 8];
            ah[mt][2] = Ah[cur][tg + 4][m0];
            ah[mt][3] = Ah[cur][tg + 4][m0 + 8];
            al[mt][0] = Al[cur][tg    ][m0];
            al[mt][1] = Al[cur][tg    ][m0 + 8];
            al[mt][2] = Al[cur][tg + 4][m0];
            al[mt][3] = Al[cur][tg + 4][m0 + 8];
        }
#pragma unroll
        for (int nt = 0; nt < 4; nt++) {
            int n0 = n_base + nt * 8 + g;
            bh[nt][0] = Bh[cur][tg    ][n0];
            bh[nt][1] = Bh[cur][tg + 4][n0];
            bl[nt][0] = Bl[cur][tg    ][n0];
            bl[nt][1] = Bl[cur][tg + 4][n0];
        }

        // ---- 3-pass tf32 MMA: hi*hi + hi*lo + lo*hi ----
#pragma unroll
        for (int mt = 0; mt < 4; mt++)
#pragma unroll
            for (int nt = 0; nt < 4; nt++) {
                mma_tf32(c[mt][nt], ah[mt], bh[nt]);
                mma_tf32(c[mt][nt], ah[mt], bl[nt]);
                mma_tf32(c[mt][nt], al[mt], bh[nt]);
            }

        if (more) stage(cur ^ 1, av, bv);
        __syncthreads();
        cur ^= 1;
    }

    // ---- epilogue ----
#pragma unroll
    for (int mt = 0; mt < 4; mt++) {
#pragma unroll
        for (int nt = 0; nt < 4; nt++) {
            int r0 = row0 + m_base + mt * 16 + g;
            int cc = col0 + n_base + nt * 8 + tg * 2;
#pragma unroll
            for (int half = 0; half < 2; half++) {
                int r = r0 + half * 8;
                if (r >= Mrows) continue;
                float v0 = c[mt][nt][half * 2 + 0];
                float v1 = c[mt][nt][half * 2 + 1];
                if (EPI == 0) { v0 += bias[cc]; v1 += bias[cc + 1]; }
                else if (EPI == 1) {
                    float rvv = rv[r];
                    v0 = expf(v0 - rvv) * 0.0625f;
                    v1 = expf(v1 - rvv) * 0.0625f;
                }
                else if (EPI == 2) {
                    float d = rv[r] + EPS;
                    v0 = v0 / d;
                    v1 = v1 / d;
                }
                else if (EPI == 3) {
                    v0 += bias[cc]     + res[(size_t)r * ldc + cc];
                    v1 += bias[cc + 1] + res[(size_t)r * ldc + cc + 1];
                }
                else if (EPI == 4) {
                    float t0 = v0 + bias[cc];
                    float t1 = v1 + bias[cc + 1];
                    v0 = 0.5f * t0 * (1.f + erff(t0 * 0.70710678118654752f));
                    v1 = 0.5f * t1 * (1.f + erff(t1 * 0.70710678118654752f));
                }
                // EPI 5: none
                *(float2*)&C[(size_t)r * ldc + cc] = make_float2(v0, v1);
            }
        }
    }
}

// ---------------- LayerNorm: one warp per token, dim 512 ----------------
__global__ void ln_kernel(const float* __restrict__ x, const float* __restrict__ g,
                          const float* __restrict__ b, float* __restrict__ out)
{
    int warp = blockIdx.x * 8 + (threadIdx.x >> 5);
    int lane = threadIdx.x & 31;
    if (warp >= NTOK) return;
    const float* row = x + (size_t)warp * 512;
    float v[16], s = 0.f, s2 = 0.f;
#pragma unroll
    for (int i = 0; i < 16; i++) {
        v[i] = row[lane + i * 32];
        s += v[i]; s2 += v[i] * v[i];
    }
#pragma unroll
    for (int o = 16; o; o >>= 1) {
        s  += __shfl_xor_sync(0xffffffffu, s,  o);
        s2 += __shfl_xor_sync(0xffffffffu, s2, o);
    }
    float mu  = s * (1.f / 512.f);
    float var = s2 * (1.f / 512.f) - mu * mu;
    float inv = rsqrtf(var + LN_EPS);
    float* orow = out + (size_t)warp * 512;
#pragma unroll
    for (int i = 0; i < 16; i++) {
        int c = lane + i * 32;
        orow[c] = (v[i] - mu) * inv * g[c] + b[c];
    }
}

// ---------------- xd = 0.5*||k||^2 and 0.5*||q||^2 per token ----------------
__global__ void xd_kernel(const float* __restrict__ kqv,
                          float* __restrict__ xdk, float* __restrict__ xdq)
{
    int warp = blockIdx.x * 8 + (threadIdx.x >> 5);
    int lane = threadIdx.x & 31;
    if (warp >= NTOK) return;
    const float* r = kqv + (size_t)warp * 1536;
    float sk = 0.f, sq = 0.f;
#pragma unroll
    for (int i = 0; i < 16; i++) {
        float a = r[lane + i * 32];        sk += a * a;
        float b = r[512 + lane + i * 32];  sq += b * b;
    }
#pragma unroll
    for (int o = 16; o; o >>= 1) {
        sk += __shfl_xor_sync(0xffffffffu, sk, o);
        sq += __shfl_xor_sync(0xffffffffu, sq, o);
    }
    if (lane == 0) { xdk[warp] = 0.5f * sk; xdq[warp] = 0.5f * sq; }
}

// ---------------- kp column-sum over T (deterministic two-stage) ----------------
__global__ void kpsum_stage1(const float* __restrict__ kp, float* __restrict__ part)
{
    int b = blockIdx.x, chunk = blockIdx.y, m = threadIdx.x;   // 256 threads
    int t0 = chunk * 112;
    float s = 0.f;
    const float* base = kp + ((size_t)b * TSEQ + t0) * 256 + m;
    for (int t = 0; t < 112; ++t) s += base[(size_t)t * 256];
    part[((size_t)b * 28 + chunk) * 256 + m] = s;
}
__global__ void kpsum_stage2(const float* __restrict__ part, float* __restrict__ kpsum)
{
    int b = blockIdx.x, m = threadIdx.x;
    float s = 0.f;
#pragma unroll
    for (int c = 0; c < 28; ++c) s += part[((size_t)b * 28 + c) * 256 + m];
    kpsum[b * 256 + m] = s;
}

// ---------------- D[t] = qp[t,:] . kpsum[b,:] : one warp per token ----------------
__global__ void d_kernel(const float* __restrict__ qp, const float* __restrict__ kpsum,
                         float* __restrict__ D)
{
    int warp = blockIdx.x * 8 + (threadIdx.x >> 5);
    int lane = threadIdx.x & 31;
    if (warp >= NTOK) return;
    int b = warp / TSEQ;
    const float* q  = qp + (size_t)warp * 256;
    const float* ks = kpsum + b * 256;
    float s = 0.f;
#pragma unroll
    for (int i = 0; i < 8; i++) {
        int c = lane + i * 32;
        s += q[c] * ks[c];
    }
#pragma unroll
    for (int o = 16; o; o >>= 1) s += __shfl_xor_sync(0xffffffffu, s, o);
    if (lane == 0) D[warp] = s;
}

// ---------------- host launch ----------------
extern "C" void kernel_launch(void* const* d_in, const int* in_sizes, int n_in,
                              void* d_out, int out_size)
{
    const float* x      = (const float*)d_in[0];
    const float* w_kqv  = (const float*)d_in[1];
    const float* b_kqv  = (const float*)d_in[2];
    const float* w_proj = (const float*)d_in[3];
    const float* b_proj = (const float*)d_in[4];
    const float* g1     = (const float*)d_in[5];
    const float* be1    = (const float*)d_in[6];
    const float* g2     = (const float*)d_in[7];
    const float* be2    = (const float*)d_in[8];
    const float* w_mlp1 = (const float*)d_in[9];
    const float* b_mlp1 = (const float*)d_in[10];
    const float* w_mlp2 = (const float*)d_in[11];
    const float* b_mlp2 = (const float*)d_in[12];
    const float* w_rand = (const float*)d_in[13];
    float* out = (float*)d_out;

    float *h, *kqv, *kp, *qp, *xdk, *xdq, *part, *kpsum, *kptv, *Dv, *y, *x2, *h2, *u;
    cudaGetSymbolAddress((void**)&h,    g_h);
    cudaGetSymbolAddress((void**)&kqv,  g_kqv);
    cudaGetSymbolAddress((void**)&kp,   g_kp);
    cudaGetSymbolAddress((void**)&qp,   g_qp);
    cudaGetSymbolAddress((void**)&xdk,  g_xdk);
    cudaGetSymbolAddress((void**)&xdq,  g_xdq);
    cudaGetSymbolAddress((void**)&part, g_part);
    cudaGetSymbolAddress((void**)&kpsum,g_kpsum);
    cudaGetSymbolAddress((void**)&kptv, g_kptv);
    cudaGetSymbolAddress((void**)&Dv,   g_D);
    cudaGetSymbolAddress((void**)&y,    g_y);
    cudaGetSymbolAddress((void**)&x2,   g_x2);
    cudaGetSymbolAddress((void**)&h2,   g_h2);
    cudaGetSymbolAddress((void**)&u,    g_u);

    // 1) h = LN1(x)
    ln_kernel<<<NTOK / 8, 256>>>(x, g1, be1, h);

    // 2) kqv = h @ w_kqv + b_kqv                     [50176,1536]  (tf32x3)
    gemm_tf32<0,0,0><<<dim3(12, 392), 256>>>(
        h, w_kqv, kqv, NTOK, 1536, 512, 512, 1536, 1536,
        b_kqv, nullptr, nullptr, 0, 0, 0, 0);

    // 3) xd_k, xd_q
    xd_kernel<<<NTOK / 8, 256>>>(kqv, xdk, xdq);

    // 4) kp = exp(k @ w_rand^T - xd_k)/16            [50176,256]  (tf32x3, B^T)
    gemm_tf32<0,1,1><<<dim3(2, 392), 256>>>(
        kqv, w_rand, kp, NTOK, 256, 512, 1536, 512, 256,
        nullptr, xdk, nullptr, 0, 0, 0, 0);

    // 5) qp = exp(q @ w_rand^T - xd_q)/16            (tf32x3, B^T)
    gemm_tf32<0,1,1><<<dim3(2, 392), 256>>>(
        kqv + 512, w_rand, qp, NTOK, 256, 512, 1536, 512, 256,
        nullptr, xdq, nullptr, 0, 0, 0, 0);

    // 6) kpsum[b,m] = sum_t kp   (deterministic two-stage)
    kpsum_stage1<<<dim3(BATCH, 28, 1), 256>>>(kp, part);
    kpsum_stage2<<<BATCH, 256>>>(part, kpsum);

    // 7) kptv[b,n,m] = sum_t v[b,t,n]*kp[b,t,m]      per-batch (tf32x3, A^T)
    gemm_tf32<1,0,5><<<dim3(2, 4, BATCH), 256>>>(
        kqv + 1024, kp, kptv, 512, 256, TSEQ, 1536, 256, 256,
        nullptr, nullptr, nullptr,
        (long long)TSEQ * 1536, (long long)TSEQ * 256, (long long)512 * 256, 0);

    // 8) D[t] = qp . kpsum
    d_kernel<<<NTOK / 8, 256>>>(qp, kpsum, Dv);

    // 9) y = (qp @ kptv^T) / (D + eps)               per-batch (tf32x3, B^T, M-guarded)
    gemm_tf32<0,1,2><<<dim3(4, 25, BATCH), 256>>>(
        qp, kptv, y, TSEQ, 512, 256, 256, 256, 512,
        nullptr, Dv, nullptr,
        (long long)TSEQ * 256, (long long)512 * 256, (long long)TSEQ * 512, TSEQ);

    // 10) x2 = y @ w_proj + b_proj + x (residual)    (tf32x3)
    gemm_tf32<0,0,3><<<dim3(4, 392), 256>>>(
        y, w_proj, x2, NTOK, 512, 512, 512, 512, 512,
        b_proj, nullptr, x, 0, 0, 0, 0);

    // 11) h2 = LN2(x2)
    ln_kernel<<<NTOK / 8, 256>>>(x2, g2, be2, h2);

    // 12) u = gelu(h2 @ w_mlp1 + b_mlp1)             (tf32x3)
    gemm_tf32<0,0,4><<<dim3(4, 392), 256>>>(
        h2, w_mlp1, u, NTOK, 512, 512, 512, 512, 512,
        b_mlp1, nullptr, nullptr, 0, 0, 0, 0);

    // 13) out = u @ w_mlp2 + b_mlp2 + x2 (residual)  (tf32x3)
    gemm_tf32<0,0,3><<<dim3(4, 392), 256>>>(
        u, w_mlp2, out, NTOK, 512, 512, 512, 512, 512,
        b_mlp2, nullptr, x2, 0, 0, 0, 0);

    (void)in_sizes; (void)n_in; (void)out_size;
}

// round 17
// speedup vs baseline: 1.1563x; 1.0052x over previous
#include <cuda_runtime.h>
#include <math.h>
#include <stdint.h>

// ---------------- problem constants ----------------
#define NTOK  50176        // B*T
#define TSEQ  3136
#define BATCH 16
#define LN_EPS 1e-5f
#define EPS    1e-8f

// ---------------- device scratch (no mallocs allowed) ----------------
__device__ float g_h   [(size_t)NTOK * 512];
__device__ float g_kqv [(size_t)NTOK * 1536];
__device__ float g_kp  [(size_t)NTOK * 256];
__device__ float g_qp  [(size_t)NTOK * 256];
__device__ float g_xdk [NTOK];
__device__ float g_xdq [NTOK];
__device__ float g_part[BATCH * 28 * 256];
__device__ float g_kpsum[BATCH * 256];
__device__ float g_kptv[(size_t)BATCH * 512 * 256];
__device__ float g_D   [NTOK];
__device__ float g_y   [(size_t)NTOK * 512];
__device__ float g_x2  [(size_t)NTOK * 512];
__device__ float g_h2  [(size_t)NTOK * 512];
__device__ float g_u   [(size_t)NTOK * 512];

// =====================================================================
// tf32x3 tensor-core GEMM (fp32-accurate via hi/lo split, 3 MMAs)
// C[M,N] = epi(A @ B), fp32 in/out.  2 CTAs/SM (launch_bounds).
// AMODE 0: A[m*lda+k]      AMODE 1: A[k*lda+m]  (A^T given; requires M%128==0)
// BMODE 0: B[k*ldb+n]      BMODE 1: B[n*ldb+k]  (B^T given; requires N%128==0)
// Requires N%128==0, K%8==0. M guarded (any M).
// EPI 0: +bias  1: exp(acc-rowv[r])/16  2: acc/(rowv[r]+EPS)
// EPI 3: +bias+res  4: gelu_exact(+bias)  5: none
// =====================================================================
__device__ __forceinline__ void tf32_split(float x, float& hi, float& lo)
{
    uint32_t u;
    asm("cvt.rna.tf32.f32 %0, %1;" : "=r"(u) : "f"(x));
    hi = __uint_as_float(u);
    float r = x - hi;
    asm("cvt.rna.tf32.f32 %0, %1;" : "=r"(u) : "f"(r));
    lo = __uint_as_float(u);
}

__device__ __forceinline__ void mma_tf32(float* c, const float* a, const float* b)
{
    asm volatile(
        "mma.sync.aligned.m16n8k8.row.col.f32.tf32.tf32.f32 "
        "{%0,%1,%2,%3}, {%4,%5,%6,%7}, {%8,%9}, {%0,%1,%2,%3};"
        : "+f"(c[0]), "+f"(c[1]), "+f"(c[2]), "+f"(c[3])
        : "r"(__float_as_uint(a[0])), "r"(__float_as_uint(a[1])),
          "r"(__float_as_uint(a[2])), "r"(__float_as_uint(a[3])),
          "r"(__float_as_uint(b[0])), "r"(__float_as_uint(b[1])));
}

template<int AMODE, int BMODE, int EPI>
__global__ void __launch_bounds__(256, 2)
gemm_tf32(const float* __restrict__ A, const float* __restrict__ B,
          float* __restrict__ C,
          int Mrows, int Ncols, int K, int lda, int ldb, int ldc,
          const float* __restrict__ bias,
          const float* __restrict__ rowv,
          const float* __restrict__ res,
          long long sA, long long sB, long long sC, long long sRow)
{
    constexpr int BM = 128, BN = 128, BK = 8;
    __shared__ float Ah[2][BK][BM + 4], Al[2][BK][BM + 4];
    __shared__ float Bh[2][BK][BN + 4], Bl[2][BK][BN + 4];

    const int z = blockIdx.z;
    A += (long long)z * sA;
    B += (long long)z * sB;
    C += (long long)z * sC;
    const float* rv = rowv ? rowv + (long long)z * sRow : nullptr;

    const int tid  = threadIdx.x;
    const int row0 = blockIdx.y * BM, col0 = blockIdx.x * BN;

    // ---- gmem load mapping (one float4 for A, one for B, per thread) ----
    const int arow  = (AMODE == 0) ? (tid >> 1) : 0;
    const int acol4 = (AMODE == 0) ? ((tid & 1) * 4) : 0;
    const int ak    = (AMODE == 1) ? (tid >> 5) : 0;
    const int am4   = (AMODE == 1) ? ((tid & 31) * 4) : 0;
    const int bk    = (BMODE == 0) ? (tid >> 5) : 0;
    const int bn4   = (BMODE == 0) ? ((tid & 31) * 4) : 0;
    const int bn    = (BMODE == 1) ? (tid >> 1) : 0;
    const int bk4   = (BMODE == 1) ? ((tid & 1) * 4) : 0;

    // warp/fragment mapping (verified: rel_err 8.6e-7 on round-12/15 passes)
    const int warp = tid >> 5, lane = tid & 31;
    const int wm = warp & 1, wn = warp >> 1;       // 2 x 4 warp grid
    const int g = lane >> 2, tg = lane & 3;
    const int m_base = wm * 64, n_base = wn * 32;

    float c[4][4][4];
#pragma unroll
    for (int mt = 0; mt < 4; mt++)
#pragma unroll
        for (int nt = 0; nt < 4; nt++)
#pragma unroll
            for (int e = 0; e < 4; e++) c[mt][nt][e] = 0.f;

    auto loadA = [&](int k0) -> float4 {
        if (AMODE == 0) {
            int gm = row0 + arow;
            if (gm < Mrows)
                return *(const float4*)&A[(size_t)gm * lda + k0 + acol4];
            return make_float4(0.f, 0.f, 0.f, 0.f);
        } else {
            // AMODE 1 requires M%128==0 (call site: kptv M=512)
            return *(const float4*)&A[(size_t)(k0 + ak) * lda + row0 + am4];
        }
    };
    auto loadB = [&](int k0) -> float4 {
        if (BMODE == 0)
            return *(const float4*)&B[(size_t)(k0 + bk) * ldb + col0 + bn4];
        else
            return *(const float4*)&B[(size_t)(col0 + bn) * ldb + k0 + bk4];
    };
    auto stage = [&](int buf, float4 av, float4 bv) {
        float hi, lo;
        float a[4] = {av.x, av.y, av.z, av.w};
        float b[4] = {bv.x, bv.y, bv.z, bv.w};
#pragma unroll
        for (int j = 0; j < 4; j++) {
            tf32_split(a[j], hi, lo);
            if (AMODE == 0) { Ah[buf][acol4 + j][arow] = hi; Al[buf][acol4 + j][arow] = lo; }
            else            { Ah[buf][ak][am4 + j]     = hi; Al[buf][ak][am4 + j]     = lo; }
        }
#pragma unroll
        for (int j = 0; j < 4; j++) {
            tf32_split(b[j], hi, lo);
            if (BMODE == 0) { Bh[buf][bk][bn4 + j] = hi; Bl[buf][bk][bn4 + j] = lo; }
            else            { Bh[buf][bk4 + j][bn] = hi; Bl[buf][bk4 + j][bn] = lo; }
        }
    };

    // ---- preload k0 = 0 ----
    stage(0, loadA(0), loadB(0));
    __syncthreads();

    int cur = 0;
    for (int k0 = 0; k0 < K; k0 += BK) {
        const bool more = (k0 + BK) < K;
        float4 av, bv;
        if (more) { av = loadA(k0 + BK); bv = loadB(k0 + BK); }

        // ---- load fragments from smem ----
        float ah[4][4], al[4][4], bh[4][2], bl[4][2];
#pragma unroll
        for (int mt = 0; mt < 4; mt++) {
            int m0 = m_base + mt * 16 + g;
            ah[mt][0] = Ah[cur][tg    ][m0];
            ah[mt][1] = Ah[cur][tg    ][m0 + 8];
            ah[mt][2] = Ah[cur][tg + 4][m0];
            ah[mt][3] = Ah[cur][tg + 4][m0 + 8];
            al[mt][0] = Al[cur][tg    ][m0];
            al[mt][1] = Al[cur][tg    ][m0 + 8];
            al[mt][2] = Al[cur][tg + 4][m0];
            al[mt][3] = Al[cur][tg + 4][m0 + 8];
        }
#pragma unroll
        for (int nt = 0; nt < 4; nt++) {
            int n0 = n_base + nt * 8 + g;
            bh[nt][0] = Bh[cur][tg    ][n0];
            bh[nt][1] = Bh[cur][tg + 4][n0];
            bl[nt][0] = Bl[cur][tg    ][n0];
            bl[nt][1] = Bl[cur][tg + 4][n0];
        }

        // ---- 3-pass tf32 MMA: hi*hi + hi*lo + lo*hi ----
#pragma unroll
        for (int mt = 0; mt < 4; mt++)
#pragma unroll
            for (int nt = 0; nt < 4; nt++) {
                mma_tf32(c[mt][nt], ah[mt], bh[nt]);
                mma_tf32(c[mt][nt], ah[mt], bl[nt]);
                mma_tf32(c[mt][nt], al[mt], bh[nt]);
            }

        if (more) stage(cur ^ 1, av, bv);
        __syncthreads();
        cur ^= 1;
    }

    // ---- epilogue ----
#pragma unroll
    for (int mt = 0; mt < 4; mt++) {
#pragma unroll
        for (int nt = 0; nt < 4; nt++) {
            int r0 = row0 + m_base + mt * 16 + g;
            int cc = col0 + n_base + nt * 8 + tg * 2;
#pragma unroll
            for (int half = 0; half < 2; half++) {
                int r = r0 + half * 8;
                if (r >= Mrows) continue;
                float v0 = c[mt][nt][half * 2 + 0];
                float v1 = c[mt][nt][half * 2 + 1];
                if (EPI == 0) { v0 += bias[cc]; v1 += bias[cc + 1]; }
                else if (EPI == 1) {
                    float rvv = rv[r];
                    v0 = expf(v0 - rvv) * 0.0625f;
                    v1 = expf(v1 - rvv) * 0.0625f;
                }
                else if (EPI == 2) {
                    float d = rv[r] + EPS;
                    v0 = v0 / d;
                    v1 = v1 / d;
                }
                else if (EPI == 3) {
                    v0 += bias[cc]     + res[(size_t)r * ldc + cc];
                    v1 += bias[cc + 1] + res[(size_t)r * ldc + cc + 1];
                }
                else if (EPI == 4) {
                    float t0 = v0 + bias[cc];
                    float t1 = v1 + bias[cc + 1];
                    v0 = 0.5f * t0 * (1.f + erff(t0 * 0.70710678118654752f));
                    v1 = 0.5f * t1 * (1.f + erff(t1 * 0.70710678118654752f));
                }
                // EPI 5: none
                *(float2*)&C[(size_t)r * ldc + cc] = make_float2(v0, v1);
            }
        }
    }
}

// ---------------- LayerNorm: one warp per token, dim 512 ----------------
__global__ void ln_kernel(const float* __restrict__ x, const float* __restrict__ g,
                          const float* __restrict__ b, float* __restrict__ out)
{
    int warp = blockIdx.x * 8 + (threadIdx.x >> 5);
    int lane = threadIdx.x & 31;
    if (warp >= NTOK) return;
    const float* row = x + (size_t)warp * 512;
    float v[16], s = 0.f, s2 = 0.f;
#pragma unroll
    for (int i = 0; i < 16; i++) {
        v[i] = row[lane + i * 32];
        s += v[i]; s2 += v[i] * v[i];
    }
#pragma unroll
    for (int o = 16; o; o >>= 1) {
        s  += __shfl_xor_sync(0xffffffffu, s,  o);
        s2 += __shfl_xor_sync(0xffffffffu, s2, o);
    }
    float mu  = s * (1.f / 512.f);
    float var = s2 * (1.f / 512.f) - mu * mu;
    float inv = rsqrtf(var + LN_EPS);
    float* orow = out + (size_t)warp * 512;
#pragma unroll
    for (int i = 0; i < 16; i++) {
        int c = lane + i * 32;
        orow[c] = (v[i] - mu) * inv * g[c] + b[c];
    }
}

// ---------------- xd = 0.5*||k||^2 and 0.5*||q||^2 per token ----------------
__global__ void xd_kernel(const float* __restrict__ kqv,
                          float* __restrict__ xdk, float* __restrict__ xdq)
{
    int warp = blockIdx.x * 8 + (threadIdx.x >> 5);
    int lane = threadIdx.x & 31;
    if (warp >= NTOK) return;
    const float* r = kqv + (size_t)warp * 1536;
    float sk = 0.f, sq = 0.f;
#pragma unroll
    for (int i = 0; i < 16; i++) {
        float a = r[lane + i * 32];        sk += a * a;
        float b = r[512 + lane + i * 32];  sq += b * b;
    }
#pragma unroll
    for (int o = 16; o; o >>= 1) {
        sk += __shfl_xor_sync(0xffffffffu, sk, o);
        sq += __shfl_xor_sync(0xffffffffu, sq, o);
    }
    if (lane == 0) { xdk[warp] = 0.5f * sk; xdq[warp] = 0.5f * sq; }
}

// ---------------- kp column-sum over T (deterministic two-stage) ----------------
__global__ void kpsum_stage1(const float* __restrict__ kp, float* __restrict__ part)
{
    int b = blockIdx.x, chunk = blockIdx.y, m = threadIdx.x;   // 256 threads
    int t0 = chunk * 112;
    float s = 0.f;
    const float* base = kp + ((size_t)b * TSEQ + t0) * 256 + m;
    for (int t = 0; t < 112; ++t) s += base[(size_t)t * 256];
    part[((size_t)b * 28 + chunk) * 256 + m] = s;
}
__global__ void kpsum_stage2(const float* __restrict__ part, float* __restrict__ kpsum)
{
    int b = blockIdx.x, m = threadIdx.x;
    float s = 0.f;
#pragma unroll
    for (int c = 0; c < 28; ++c) s += part[((size_t)b * 28 + c) * 256 + m];
    kpsum[b * 256 + m] = s;
}

// ---------------- D[t] = qp[t,:] . kpsum[b,:] : one warp per token ----------------
__global__ void d_kernel(const float* __restrict__ qp, const float* __restrict__ kpsum,
                         float* __restrict__ D)
{
    int warp = blockIdx.x * 8 + (threadIdx.x >> 5);
    int lane = threadIdx.x & 31;
    if (warp >= NTOK) return;
    int b = warp / TSEQ;
    const float* q  = qp + (size_t)warp * 256;
    const float* ks = kpsum + b * 256;
    float s = 0.f;
#pragma unroll
    for (int i = 0; i < 8; i++) {
        int c = lane + i * 32;
        s += q[c] * ks[c];
    }
#pragma unroll
    for (int o = 16; o; o >>= 1) s += __shfl_xor_sync(0xffffffffu, s, o);
    if (lane == 0) D[warp] = s;
}

// ---------------- host launch ----------------
extern "C" void kernel_launch(void* const* d_in, const int* in_sizes, int n_in,
                              void* d_out, int out_size)
{
    const float* x      = (const float*)d_in[0];
    const float* w_kqv  = (const float*)d_in[1];
    const float* b_kqv  = (const float*)d_in[2];
    const float* w_proj = (const float*)d_in[3];
    const float* b_proj = (const float*)d_in[4];
    const float* g1     = (const float*)d_in[5];
    const float* be1    = (const float*)d_in[6];
    const float* g2     = (const float*)d_in[7];
    const float* be2    = (const float*)d_in[8];
    const float* w_mlp1 = (const float*)d_in[9];
    const float* b_mlp1 = (const float*)d_in[10];
    const float* w_mlp2 = (const float*)d_in[11];
    const float* b_mlp2 = (const float*)d_in[12];
    const float* w_rand = (const float*)d_in[13];
    float* out = (float*)d_out;

    float *h, *kqv, *kp, *qp, *xdk, *xdq, *part, *kpsum, *kptv, *Dv, *y, *x2, *h2, *u;
    cudaGetSymbolAddress((void**)&h,    g_h);
    cudaGetSymbolAddress((void**)&kqv,  g_kqv);
    cudaGetSymbolAddress((void**)&kp,   g_kp);
    cudaGetSymbolAddress((void**)&qp,   g_qp);
    cudaGetSymbolAddress((void**)&xdk,  g_xdk);
    cudaGetSymbolAddress((void**)&xdq,  g_xdq);
    cudaGetSymbolAddress((void**)&part, g_part);
    cudaGetSymbolAddress((void**)&kpsum,g_kpsum);
    cudaGetSymbolAddress((void**)&kptv, g_kptv);
    cudaGetSymbolAddress((void**)&Dv,   g_D);
    cudaGetSymbolAddress((void**)&y,    g_y);
    cudaGetSymbolAddress((void**)&x2,   g_x2);
    cudaGetSymbolAddress((void**)&h2,   g_h2);
    cudaGetSymbolAddress((void**)&u,    g_u);

    // 1) h = LN1(x)
    ln_kernel<<<NTOK / 8, 256>>>(x, g1, be1, h);

    // 2) kqv = h @ w_kqv + b_kqv                     [50176,1536]  (tf32x3)
    gemm_tf32<0,0,0><<<dim3(12, 392), 256>>>(
        h, w_kqv, kqv, NTOK, 1536, 512, 512, 1536, 1536,
        b_kqv, nullptr, nullptr, 0, 0, 0, 0);

    // 3) xd_k, xd_q
    xd_kernel<<<NTOK / 8, 256>>>(kqv, xdk, xdq);

    // 4) kp = exp(k @ w_rand^T - xd_k)/16            [50176,256]  (tf32x3, B^T)
    gemm_tf32<0,1,1><<<dim3(2, 392), 256>>>(
        kqv, w_rand, kp, NTOK, 256, 512, 1536, 512, 256,
        nullptr, xdk, nullptr, 0, 0, 0, 0);

    // 5) qp = exp(q @ w_rand^T - xd_q)/16            (tf32x3, B^T)
    gemm_tf32<0,1,1><<<dim3(2, 392), 256>>>(
        kqv + 512, w_rand, qp, NTOK, 256, 512, 1536, 512, 256,
        nullptr, xdq, nullptr, 0, 0, 0, 0);

    // 6) kpsum[b,m] = sum_t kp   (deterministic two-stage)
    kpsum_stage1<<<dim3(BATCH, 28, 1), 256>>>(kp, part);
    kpsum_stage2<<<BATCH, 256>>>(part, kpsum);

    // 7) kptv[b,n,m] = sum_t v[b,t,n]*kp[b,t,m]      per-batch (tf32x3, A^T)
    gemm_tf32<1,0,5><<<dim3(2, 4, BATCH), 256>>>(
        kqv + 1024, kp, kptv, 512, 256, TSEQ, 1536, 256, 256,
        nullptr, nullptr, nullptr,
        (long long)TSEQ * 1536, (long long)TSEQ * 256, (long long)512 * 256, 0);

    // 8) D[t] = qp . kpsum
    d_kernel<<<NTOK / 8, 256>>>(qp, kpsum, Dv);

    // 9) y = (qp @ kptv^T) / (D + eps)               per-batch (tf32x3, B^T, M-guarded)
    gemm_tf32<0,1,2><<<dim3(4, 25, BATCH), 256>>>(
        qp, kptv, y, TSEQ, 512, 256, 256, 256, 512,
        nullptr, Dv, nullptr,
        (long long)TSEQ * 256, (long long)512 * 256, (long long)TSEQ * 512, TSEQ);

    // 10) x2 = y @ w_proj + b_proj + x (residual)    (tf32x3)
    gemm_tf32<0,0,3><<<dim3(4, 392), 256>>>(
        y, w_proj, x2, NTOK, 512, 512, 512, 512, 512,
        b_proj, nullptr, x, 0, 0, 0, 0);

    // 11) h2 = LN2(x2)
    ln_kernel<<<NTOK / 8, 256>>>(x2, g2, be2, h2);

    // 12) u = gelu(h2 @ w_mlp1 + b_mlp1)             (tf32x3)
    gemm_tf32<0,0,4><<<dim3(4, 392), 256>>>(
        h2, w_mlp1, u, NTOK, 512, 512, 512, 512, 512,
        b_mlp1, nullptr, nullptr, 0, 0, 0, 0);

    // 13) out = u @ w_mlp2 + b_mlp2 + x2 (residual)  (tf32x3)
    gemm_tf32<0,0,3><<<dim3(4, 392), 256>>>(
        u, w_mlp2, out, NTOK, 512, 512, 512, 512, 512,
        b_mlp2, nullptr, x2, 0, 0, 0, 0);

    (void)in_sizes; (void)n_in; (void)out_size;
}